// round 9
// baseline (speedup 1.0000x reference)
#include <cuda_runtime.h>

// Attn_Pred_Model: out[slice][s][b] =
//   ( sum_{i=0..7} alpha*beta^i * x[slice][s-1-i][b] + pb_fwd[b]
//     + pb_bwd[((s>>6)-b) & 63] ) * mask(s,b)
// mask(s,b) = 1 iff s >= max(128, 64*(b+1))  (band-constant, band = 64 rows)
//
// R8: float4 restructure of the confirmed-best R2 config. Each thread owns
// 4 columns (16B accesses); half-warp = one contiguous 256B row segment
// (lanes 0-15 -> chunk 2m, lanes 16-31 -> chunk 2m+1). CHUNK=128 keeps
// 131072 threads / 1024 blocks = single full-residency wave. Halves
// LDG/STG instruction count and L1tex wavefronts per byte. Horner
// evaluation drops the coefficient array (register relief);
// __launch_bounds__(128,7) pins 7 blocks/SM to preserve the single wave.
// Triangle-dead reads still predicated off per-lane (~49% of read bytes).

#define S_DIM   4096
#define B_DIM   64
#define SLICES  256
#define PAST    8
#define CHUNK   128              // rows per thread
#define N_CHUNK (S_DIM / CHUNK)  // 32

__global__ __launch_bounds__(128, 7)
void attn_pred_kernel(const float* __restrict__ x,
                      const float* __restrict__ pb_fwd,
                      const float* __restrict__ pb_bwd,
                      const float* __restrict__ alpha_p,
                      const float* __restrict__ beta_p,
                      float* __restrict__ out)
{
    const int t     = blockIdx.x * blockDim.x + threadIdx.x;
    const int lane4 = t & 15;        // column group: cols 4*lane4 .. 4*lane4+3
    const int rest  = t >> 4;
    const int chunk = rest & (N_CHUNK - 1);
    const int slice = rest >> 5;     // rest / N_CHUNK

    const float alpha = alpha_p[0];
    const float beta  = beta_p[0];

    const int c0 = 4 * lane4;

    // per-column biases (pb_fwd part; pb_bwd part added per band)
    const float pf0 = __ldg(&pb_fwd[c0 + 0]);
    const float pf1 = __ldg(&pb_fwd[c0 + 1]);
    const float pf2 = __ldg(&pb_fwd[c0 + 2]);
    const float pf3 = __ldg(&pb_fwd[c0 + 3]);

    // first active band per column: active iff band q >= qact_j
    const int qa0 = (c0 + 1 < 2) ? 2 : (c0 + 1);  // max(2, c+1)
    const int qa1 = c0 + 2;   // cols >= 1 activate at c+1 >= 2 naturally
    const int qa2 = c0 + 3;
    const int qa3 = c0 + 4;
    // earliest-activating column in this group is c0:
    // x[s] feeds out[s+1..s+8], so load needed iff s + 8 >= 64*qa0
    const int ld_thresh = (qa0 << 6) - 8;        // always >= 120 > 0

    const size_t slice_off = (size_t)slice * S_DIM * (B_DIM / 4); // float4 units
    const float4* __restrict__ xin  = (const float4*)x  + slice_off + lane4;
    float4*       __restrict__ xout = (float4*)out      + slice_off + lane4;

    const int s0 = chunk * CHUNK;

    // rolling window: w[i] = x[s-1-i] for current s (= s0 at start)
    float4 w[PAST];
    #pragma unroll
    for (int i = 0; i < PAST; i++) {
        const int sr = s0 - 1 - i;
        w[i] = (sr >= ld_thresh) ? xin[(size_t)sr * 16]
                                 : make_float4(0.f, 0.f, 0.f, 0.f);
    }

    #pragma unroll
    for (int band = 0; band < CHUNK / 64; band++) {
        const int q = (s0 >> 6) + band;          // bucket row, constant in band
        const float b0v = pf0 + __ldg(&pb_bwd[(q - (c0 + 0)) & 63]);
        const float b1v = pf1 + __ldg(&pb_bwd[(q - (c0 + 1)) & 63]);
        const float b2v = pf2 + __ldg(&pb_bwd[(q - (c0 + 2)) & 63]);
        const float b3v = pf3 + __ldg(&pb_bwd[(q - (c0 + 3)) & 63]);
        const float m0 = (q >= qa0) ? 1.f : 0.f;
        const float m1 = (q >= qa1) ? 1.f : 0.f;
        const float m2 = (q >= qa2) ? 1.f : 0.f;
        const float m3 = (q >= qa3) ? 1.f : 0.f;
        const int sbase = q * 64;

        #pragma unroll 8   // depth == PAST so window shift is free register rotation
        for (int r = 0; r < 64; r++) {
            const int s = sbase + r;
            // predicated load: dead-triangle lanes fetch nothing from DRAM
            const float4 cur = (s >= ld_thresh) ? xin[(size_t)s * 16]
                                                : make_float4(0.f, 0.f, 0.f, 0.f);

            // Horner: h = w0 + beta*(w1 + beta*(w2 + ... + beta*w7))
            float hx = w[PAST - 1].x, hy = w[PAST - 1].y;
            float hz = w[PAST - 1].z, hw = w[PAST - 1].w;
            #pragma unroll
            for (int i = PAST - 2; i >= 0; i--) {
                hx = fmaf(beta, hx, w[i].x);
                hy = fmaf(beta, hy, w[i].y);
                hz = fmaf(beta, hz, w[i].z);
                hw = fmaf(beta, hw, w[i].w);
            }

            float4 o;
            o.x = m0 * fmaf(alpha, hx, b0v);
            o.y = m1 * fmaf(alpha, hy, b1v);
            o.z = m2 * fmaf(alpha, hz, b2v);
            o.w = m3 * fmaf(alpha, hw, b3v);
            xout[(size_t)s * 16] = o;

            #pragma unroll
            for (int i = PAST - 1; i > 0; i--) w[i] = w[i - 1];
            w[0] = cur;
        }
    }
}

extern "C" void kernel_launch(void* const* d_in, const int* in_sizes, int n_in,
                              void* d_out, int out_size)
{
    // metadata order: x, pb_fwd, pb_bwd, alpha, beta, arange2, mask
    const float* x      = (const float*)d_in[0];
    const float* pb_fwd = (const float*)d_in[1];
    const float* pb_bwd = (const float*)d_in[2];
    const float* alpha  = (const float*)d_in[3];
    const float* beta   = (const float*)d_in[4];
    // arange2 (d_in[5]) and mask (d_in[6]) are reproduced analytically in-kernel.

    const int total_threads = SLICES * N_CHUNK * 16;  // 131072
    const int block = 128;
    attn_pred_kernel<<<total_threads / block, block>>>(
        x, pb_fwd, pb_bwd, alpha, beta, (float*)d_out);
}